// round 8
// baseline (speedup 1.0000x reference)
#include <cuda_runtime.h>

// y[token, o] = sum_e cos(x[token, e] + theta[e]) * W[o, e]
// tokens = 128 * 8192 = 1,048,576 ; E = O = 16
//
// Coalesced mapping: one thread per FLAT float4 index f (f = token*4 + quad).
//  - LDG.128 x4[f]: warp covers 512 contiguous bytes -> 4 lines/instr (min).
//  - lanes 4a..4a+3 hold the 4 quads of one token; full z vector exchanged
//    via __shfl_sync width=4 (no smem staging, no extra syncs).
//  - lane with quad b computes outputs o = 4b..4b+3 and stores y4[f]
//    (same flat index) -> stores also perfectly coalesced.
//  - W rows read from shared as all-lane broadcasts (conflict-free).

#define EMBED 16
#define TOKENS (128 * 8192)
#define BLOCK 256
#define NQUADS (TOKENS * 4)

__global__ __launch_bounds__(BLOCK) void qattn_kernel(
    const float4* __restrict__ x4,      // [TOKENS*4] flat float4
    const float4* __restrict__ theta4,  // [4] (16 floats)
    const float4* __restrict__ w4,      // [64] = W[16][4 quads]
    float4*       __restrict__ y4)      // [TOKENS*4]
{
    __shared__ float4 s_w[EMBED * 4];   // s_w[o*4 + q]

    if (threadIdx.x < EMBED * 4) s_w[threadIdx.x] = w4[threadIdx.x];
    __syncthreads();

    unsigned f = blockIdx.x * BLOCK + threadIdx.x;   // flat float4 index
    unsigned b = f & 3;                              // quad owned by this lane

    // ---- load + RX + measure: z quad for (token, elements 4b..4b+3) ----
    float4 xv = x4[f];
    float4 th = __ldg(&theta4[b]);       // broadcast among lanes with same b
    float z0 = __cosf(xv.x + th.x);
    float z1 = __cosf(xv.y + th.y);
    float z2 = __cosf(xv.z + th.z);
    float z3 = __cosf(xv.w + th.w);

    // ---- gather full 16-wide z of this token via width-4 shuffles ----
    float zf[EMBED];
    #pragma unroll
    for (int qe = 0; qe < 4; ++qe) {
        zf[4*qe + 0] = __shfl_sync(0xffffffffu, z0, qe, 4);
        zf[4*qe + 1] = __shfl_sync(0xffffffffu, z1, qe, 4);
        zf[4*qe + 2] = __shfl_sync(0xffffffffu, z2, qe, 4);
        zf[4*qe + 3] = __shfl_sync(0xffffffffu, z3, qe, 4);
    }

    // ---- this lane computes outputs o = 4b+j, j = 0..3 ----
    float out[4];
    #pragma unroll
    for (int j = 0; j < 4; ++j) {
        unsigned o = 4*b + j;
        float4 w0 = s_w[o*4 + 0];   // all-lane broadcast LDS (addr same mod 128)
        float4 w1 = s_w[o*4 + 1];
        float4 w2 = s_w[o*4 + 2];
        float4 w3 = s_w[o*4 + 3];
        float acc;
        acc  = zf[ 0] * w0.x;
        acc = fmaf(zf[ 1], w0.y, acc);
        acc = fmaf(zf[ 2], w0.z, acc);
        acc = fmaf(zf[ 3], w0.w, acc);
        acc = fmaf(zf[ 4], w1.x, acc);
        acc = fmaf(zf[ 5], w1.y, acc);
        acc = fmaf(zf[ 6], w1.z, acc);
        acc = fmaf(zf[ 7], w1.w, acc);
        acc = fmaf(zf[ 8], w2.x, acc);
        acc = fmaf(zf[ 9], w2.y, acc);
        acc = fmaf(zf[10], w2.z, acc);
        acc = fmaf(zf[11], w2.w, acc);
        acc = fmaf(zf[12], w3.x, acc);
        acc = fmaf(zf[13], w3.y, acc);
        acc = fmaf(zf[14], w3.z, acc);
        acc = fmaf(zf[15], w3.w, acc);
        out[j] = acc;
    }

    // y4[f] holds y[token][4b..4b+3] == exactly what this lane computed
    y4[f] = make_float4(out[0], out[1], out[2], out[3]);
}

extern "C" void kernel_launch(void* const* d_in, const int* in_sizes, int n_in,
                              void* d_out, int out_size)
{
    const float4* x4    = (const float4*)d_in[0];
    const float4* th4   = (const float4*)d_in[1];
    const float4* w4    = (const float4*)d_in[2];
    float4*       y4    = (float4*)d_out;

    qattn_kernel<<<NQUADS / BLOCK, BLOCK>>>(x4, th4, w4, y4);
}

// round 9
// speedup vs baseline: 3.5160x; 3.5160x over previous
#include <cuda_runtime.h>

// y[token, o] = sum_e cos(x[token, e] + theta[e]) * W[o, e]
// tokens = 128 * 8192 = 1,048,576 ; E = O = 16
//
// One thread per token (R1 structure: broadcast W, 256 FMA/thread), but all
// global traffic is flat-coalesced and transposed through an xor-swizzled
// smem staging buffer:
//   - stage in : 4x coalesced LDG.128 per thread -> smem rows (swizzled cols)
//   - compute  : each thread reads its own token row (conflict-free LDS.128),
//                cos, then 16x16 dot with all-lane-broadcast W (N=1, free)
//   - stage out: swizzled STS, then 4x coalesced STG.128
// Swizzle col = q ^ ((token>>1)&3): both the linear-staging phase (2 tokens
// per 8-lane phase -> bank-group bases {0..3} vs {4..7}, disjoint) and the
// row-read phase (tokens 2 apart get different cols) are conflict-free.

#define EMBED 16
#define TOKENS (128 * 8192)
#define BLOCK 256

__global__ __launch_bounds__(BLOCK) void qattn_kernel(
    const float4* __restrict__ x4,      // [TOKENS*4] flat float4
    const float4* __restrict__ theta4,  // [4]  (16 floats)
    const float4* __restrict__ w4,      // [64] = W[16 rows][4 quads]
    float4*       __restrict__ y4)      // [TOKENS*4]
{
    __shared__ float4 s_stage[BLOCK * 4];   // 16 KB staging (x, then reused for y)
    __shared__ float4 s_w[EMBED * 4];       // W[o][q]
    __shared__ float4 s_th[4];              // theta quads

    int tid = threadIdx.x;
    if (tid < EMBED * 4) s_w[tid]  = w4[tid];
    if (tid < 4)         s_th[tid] = theta4[tid];

    size_t base4 = (size_t)blockIdx.x * (BLOCK * 4);

    // ---- stage x: coalesced global loads -> swizzled smem ----
    #pragma unroll
    for (int k = 0; k < 4; ++k) {
        unsigned g   = k * BLOCK + tid;          // flat float4 index in block
        unsigned tok = g >> 2;
        unsigned q   = g & 3;
        unsigned col = q ^ ((tok >> 1) & 3);
        s_stage[tok * 4 + col] = x4[base4 + g];
    }
    __syncthreads();

    // ---- per-token: read own row (conflict-free), RX + measure ----
    unsigned c = ((unsigned)tid >> 1) & 3;
    float z[EMBED];
    #pragma unroll
    for (int q = 0; q < 4; ++q) {
        float4 xv = s_stage[tid * 4 + (q ^ c)];
        float4 th = s_th[q];
        z[4*q + 0] = __cosf(xv.x + th.x);
        z[4*q + 1] = __cosf(xv.y + th.y);
        z[4*q + 2] = __cosf(xv.z + th.z);
        z[4*q + 3] = __cosf(xv.w + th.w);
    }

    // ---- out_proj: 16 outputs, W rows as all-lane broadcasts ----
    float out[EMBED];
    #pragma unroll
    for (int o = 0; o < EMBED; ++o) {
        float4 w0 = s_w[o*4 + 0];
        float4 w1 = s_w[o*4 + 1];
        float4 w2 = s_w[o*4 + 2];
        float4 w3 = s_w[o*4 + 3];
        float acc;
        acc  = z[ 0] * w0.x;
        acc = fmaf(z[ 1], w0.y, acc);
        acc = fmaf(z[ 2], w0.z, acc);
        acc = fmaf(z[ 3], w0.w, acc);
        acc = fmaf(z[ 4], w1.x, acc);
        acc = fmaf(z[ 5], w1.y, acc);
        acc = fmaf(z[ 6], w1.z, acc);
        acc = fmaf(z[ 7], w1.w, acc);
        acc = fmaf(z[ 8], w2.x, acc);
        acc = fmaf(z[ 9], w2.y, acc);
        acc = fmaf(z[10], w2.z, acc);
        acc = fmaf(z[11], w2.w, acc);
        acc = fmaf(z[12], w3.x, acc);
        acc = fmaf(z[13], w3.y, acc);
        acc = fmaf(z[14], w3.z, acc);
        acc = fmaf(z[15], w3.w, acc);
        out[o] = acc;
    }

    __syncthreads();   // everyone done reading x stage before overwrite

    // ---- stage y: swizzled STS (conflict-free) ----
    #pragma unroll
    for (int q = 0; q < 4; ++q) {
        s_stage[tid * 4 + (q ^ c)] =
            make_float4(out[4*q + 0], out[4*q + 1], out[4*q + 2], out[4*q + 3]);
    }
    __syncthreads();

    // ---- coalesced global stores ----
    #pragma unroll
    for (int k = 0; k < 4; ++k) {
        unsigned g   = k * BLOCK + tid;
        unsigned tok = g >> 2;
        unsigned q   = g & 3;
        unsigned col = q ^ ((tok >> 1) & 3);
        y4[base4 + g] = s_stage[tok * 4 + col];
    }
}

extern "C" void kernel_launch(void* const* d_in, const int* in_sizes, int n_in,
                              void* d_out, int out_size)
{
    const float4* x4    = (const float4*)d_in[0];
    const float4* th4   = (const float4*)d_in[1];
    const float4* w4    = (const float4*)d_in[2];
    float4*       y4    = (float4*)d_out;

    qattn_kernel<<<TOKENS / BLOCK, BLOCK>>>(x4, th4, w4, y4);
}

// round 13
// speedup vs baseline: 4.0867x; 1.1623x over previous
#include <cuda_runtime.h>

// y[token, o] = sum_e cos(x[token, e] + theta[e]) * W[o, e]
// tokens = 1,048,576 ; E = O = 16
//
// T=4 tokens per thread (amortizes the W smem reads 4x — the dominant L1tex
// cost in R1/R9), xor-swizzled smem staging for coalesced global I/O (R9),
// packed fma.rn.f32x2 over element pairs (halves FMA-pipe issue; PTX-only).

#define EMBED  16
#define TOKENS (128 * 8192)
#define BLOCK  128
#define TPT    4
#define TILE   (BLOCK * TPT)      // 512 tokens / block

__device__ __forceinline__ unsigned long long pk2(float lo, float hi) {
    unsigned long long r;
    asm("mov.b64 %0, {%1,%2};" : "=l"(r) : "f"(lo), "f"(hi));
    return r;
}
__device__ __forceinline__ unsigned long long mul2(unsigned long long a, unsigned long long b) {
    unsigned long long d;
    asm("mul.rn.f32x2 %0, %1, %2;" : "=l"(d) : "l"(a), "l"(b));
    return d;
}
__device__ __forceinline__ void fma2(unsigned long long& d, unsigned long long a, unsigned long long b) {
    asm("fma.rn.f32x2 %0, %1, %2, %0;" : "+l"(d) : "l"(a), "l"(b));
}
__device__ __forceinline__ float red2(unsigned long long a) {
    float lo, hi;
    asm("mov.b64 {%0,%1}, %2;" : "=f"(lo), "=f"(hi) : "l"(a));
    return lo + hi;
}

__global__ __launch_bounds__(BLOCK) void qattn_kernel(
    const float4* __restrict__ x4,      // [TOKENS*4] flat float4
    const float4* __restrict__ theta4,  // [4]
    const float4* __restrict__ w4,      // [64] = W[16][4]
    float4*       __restrict__ y4)      // [TOKENS*4]
{
    __shared__ float4 s_stage[TILE * 4];   // 32 KB, x then reused for y
    __shared__ float4 s_w[EMBED * 4];
    __shared__ float4 s_th[4];

    int tid = threadIdx.x;
    if (tid < EMBED * 4) s_w[tid]  = w4[tid];
    if (tid < 4)         s_th[tid] = theta4[tid];

    size_t base4 = (size_t)blockIdx.x * (TILE * 4);

    // ---- stage x: coalesced LDG.128 -> swizzled STS ----
    #pragma unroll
    for (int k = 0; k < 16; ++k) {
        unsigned g   = k * BLOCK + tid;
        unsigned tok = g >> 2;
        unsigned q   = g & 3;
        s_stage[tok * 4 + (q ^ ((tok >> 1) & 3))] = x4[base4 + g];
    }
    __syncthreads();

    float4 th0 = s_th[0], th1 = s_th[1], th2 = s_th[2], th3 = s_th[3];

    // ---- z pairs for 4 tokens: t = tid + j*BLOCK (consecutive lanes ->
    //      consecutive rows: conflict-free with the R9 swizzle) ----
    unsigned long long zp[TPT][8];
    #pragma unroll
    for (int j = 0; j < TPT; ++j) {
        unsigned t = tid + j * BLOCK;
        unsigned c = (t >> 1) & 3;
        float4 a0 = s_stage[t * 4 + (0 ^ c)];
        float4 a1 = s_stage[t * 4 + (1 ^ c)];
        float4 a2 = s_stage[t * 4 + (2 ^ c)];
        float4 a3 = s_stage[t * 4 + (3 ^ c)];
        zp[j][0] = pk2(__cosf(a0.x + th0.x), __cosf(a0.y + th0.y));
        zp[j][1] = pk2(__cosf(a0.z + th0.z), __cosf(a0.w + th0.w));
        zp[j][2] = pk2(__cosf(a1.x + th1.x), __cosf(a1.y + th1.y));
        zp[j][3] = pk2(__cosf(a1.z + th1.z), __cosf(a1.w + th1.w));
        zp[j][4] = pk2(__cosf(a2.x + th2.x), __cosf(a2.y + th2.y));
        zp[j][5] = pk2(__cosf(a2.z + th2.z), __cosf(a2.w + th2.w));
        zp[j][6] = pk2(__cosf(a3.x + th3.x), __cosf(a3.y + th3.y));
        zp[j][7] = pk2(__cosf(a3.z + th3.z), __cosf(a3.w + th3.w));
    }
    __syncthreads();   // all x reads done before y overwrites staging

    // ---- out_proj by o-quads; W rows loaded once, used for 4 tokens ----
    #pragma unroll
    for (int oq = 0; oq < 4; ++oq) {
        float out[TPT][4];
        #pragma unroll
        for (int r = 0; r < 4; ++r) {
            int o = oq * 4 + r;
            float4 w0 = s_w[o*4 + 0];
            float4 w1 = s_w[o*4 + 1];
            float4 w2 = s_w[o*4 + 2];
            float4 w3 = s_w[o*4 + 3];
            unsigned long long wp0 = pk2(w0.x, w0.y), wp1 = pk2(w0.z, w0.w);
            unsigned long long wp2 = pk2(w1.x, w1.y), wp3 = pk2(w1.z, w1.w);
            unsigned long long wp4 = pk2(w2.x, w2.y), wp5 = pk2(w2.z, w2.w);
            unsigned long long wp6 = pk2(w3.x, w3.y), wp7 = pk2(w3.z, w3.w);
            #pragma unroll
            for (int j = 0; j < TPT; ++j) {
                unsigned long long acc = mul2(zp[j][0], wp0);
                fma2(acc, zp[j][1], wp1);
                fma2(acc, zp[j][2], wp2);
                fma2(acc, zp[j][3], wp3);
                fma2(acc, zp[j][4], wp4);
                fma2(acc, zp[j][5], wp5);
                fma2(acc, zp[j][6], wp6);
                fma2(acc, zp[j][7], wp7);
                out[j][r] = red2(acc);
            }
        }
        // swizzled STS of this o-quad for all 4 tokens (conflict-free)
        #pragma unroll
        for (int j = 0; j < TPT; ++j) {
            unsigned t = tid + j * BLOCK;
            s_stage[t * 4 + (oq ^ ((t >> 1) & 3))] =
                make_float4(out[j][0], out[j][1], out[j][2], out[j][3]);
        }
    }
    __syncthreads();

    // ---- store y: swizzled LDS -> coalesced STG.128 ----
    #pragma unroll
    for (int k = 0; k < 16; ++k) {
        unsigned g   = k * BLOCK + tid;
        unsigned tok = g >> 2;
        unsigned q   = g & 3;
        y4[base4 + g] = s_stage[tok * 4 + (q ^ ((tok >> 1) & 3))];
    }
}

extern "C" void kernel_launch(void* const* d_in, const int* in_sizes, int n_in,
                              void* d_out, int out_size)
{
    const float4* x4    = (const float4*)d_in[0];
    const float4* th4   = (const float4*)d_in[1];
    const float4* w4    = (const float4*)d_in[2];
    float4*       y4    = (float4*)d_out;

    qattn_kernel<<<TOKENS / TILE, BLOCK>>>(x4, th4, w4, y4);
}